// round 7
// baseline (speedup 1.0000x reference)
#include <cuda_runtime.h>
#include <math.h>

// ---------------- problem constants ----------------
static constexpr int NM  = 8192;
static constexpr int ND  = 6144;
static constexpr int NT  = 14336;      // NM + ND
static constexpr int EMM = 131072;
static constexpr int EDD = 98304;
static constexpr int EG  = 229376;
static constexpr int ETOT = EMM + EDD + EG;

static constexpr int MTILE = 64;
static constexpr int PAD = 68;          // floats per Xs row (64 + 4), keeps 16B align

// ---------------- device scratch ----------------
__device__ float g_ew[EMM + EDD];
__device__ float g_deg_m[NM];
__device__ float g_deg_d[ND];
__device__ float g_h[NT * 256];
__device__ float g_xr[NT * 256];
__device__ float g_tmp[NT * 128];
__device__ float g_x0[NT * 128];
__device__ float g_x1[NT * 64];
__device__ float g_x2[NT * 32];
__device__ int   g_cnt_m[NM];
__device__ int   g_cnt_d[ND];
__device__ int   g_cnt_g[NT];
__device__ int   g_pos[ETOT];
__device__ int   g_ptr_mm[NM + 1];
__device__ int   g_src_mm[EMM];
__device__ float g_nrm_mm[EMM];
__device__ int   g_ptr_dd[ND + 1];
__device__ int   g_src_dd[EDD];
__device__ float g_nrm_dd[EDD];
__device__ int   g_ptr_g[NT + 1];
__device__ int   g_src_g[EG];

static inline int cdiv(int a, int b) { return (a + b - 1) / b; }

// ---------------- f32x2 helpers ----------------
__device__ __forceinline__ unsigned long long pk2(float v) {
    unsigned long long r;
    asm("mov.b64 %0, {%1, %1};" : "=l"(r) : "f"(v));
    return r;
}
__device__ __forceinline__ void fma2(unsigned long long& d, unsigned long long a,
                                     unsigned long long b) {
    asm("fma.rn.f32x2 %0, %1, %2, %0;" : "+l"(d) : "l"(a), "l"(b));
}
__device__ __forceinline__ float2 upk(unsigned long long v) {
    float2 f;
    asm("mov.b64 {%0, %1}, %2;" : "=f"(f.x), "=f"(f.y) : "l"(v));
    return f;
}

// ---------------- setup kernels ----------------
__global__ void k_init() {
    int i = blockIdx.x * blockDim.x + threadIdx.x;
    if (i < NM) { g_cnt_m[i] = 0; g_deg_m[i] = 1.f; }
    if (i < ND) { g_cnt_d[i] = 0; g_deg_d[i] = 1.f; }
    if (i < NT) g_cnt_g[i] = 0;
}

__global__ void k_build(const int* __restrict__ mme, const int* __restrict__ dde,
                        const int* __restrict__ ei, const float* __restrict__ ms,
                        const float* __restrict__ ds) {
    int e = blockIdx.x * blockDim.x + threadIdx.x;
    if (e >= ETOT) return;
    if (e < EMM) {
        int s = mme[e], d = mme[EMM + e];
        float w = ms[(size_t)s * NM + d];
        g_ew[e] = w;
        atomicAdd(&g_deg_m[d], w);
        g_pos[e] = atomicAdd(&g_cnt_m[d], 1);
    } else if (e < EMM + EDD) {
        int e2 = e - EMM;
        int s = dde[e2], d = dde[EDD + e2];
        float w = ds[(size_t)s * ND + d];
        g_ew[EMM + e2] = w;
        atomicAdd(&g_deg_d[d], w);
        g_pos[e] = atomicAdd(&g_cnt_d[d], 1);
    } else {
        int e3 = e - EMM - EDD;
        int d = ei[EG + e3];
        g_pos[e] = atomicAdd(&g_cnt_g[d], 1);
    }
}

__device__ void scan_dev(const int* __restrict__ cnt, int* __restrict__ rowptr, int n) {
    __shared__ int sp[1024];
    int t = threadIdx.x;
    int per = (n + 1023) / 1024;
    int start = t * per;
    int vals[16];
    int local = 0;
    for (int j = 0; j < per; j++) {
        int i = start + j;
        vals[j] = (i < n) ? cnt[i] : 0;
        local += vals[j];
    }
    sp[t] = local;
    __syncthreads();
    for (int off = 1; off < 1024; off <<= 1) {
        int v = (t >= off) ? sp[t - off] : 0;
        __syncthreads();
        sp[t] += v;
        __syncthreads();
    }
    int ex = t ? sp[t - 1] : 0;
    for (int j = 0; j < per; j++) {
        int i = start + j;
        if (i < n) { rowptr[i] = ex; ex += vals[j]; }
    }
    if (t == 1023) rowptr[n] = sp[1023];
}
__global__ void k_scan3() {
    if (blockIdx.x == 0) scan_dev(g_cnt_m, g_ptr_mm, NM);
    else if (blockIdx.x == 1) scan_dev(g_cnt_d, g_ptr_dd, ND);
    else scan_dev(g_cnt_g, g_ptr_g, NT);
}

__global__ void k_scatter(const int* __restrict__ mme, const int* __restrict__ dde,
                          const int* __restrict__ ei) {
    int e = blockIdx.x * blockDim.x + threadIdx.x;
    if (e >= ETOT) return;
    if (e < EMM) {
        int s = mme[e], d = mme[EMM + e];
        int idx = g_ptr_mm[d] + g_pos[e];
        g_src_mm[idx] = s;
        g_nrm_mm[idx] = rsqrtf(g_deg_m[s]) * g_ew[e] * rsqrtf(g_deg_m[d]);
    } else if (e < EMM + EDD) {
        int e2 = e - EMM;
        int s = dde[e2], d = dde[EDD + e2];
        int idx = g_ptr_dd[d] + g_pos[e];
        g_src_dd[idx] = s;
        g_nrm_dd[idx] = rsqrtf(g_deg_d[s]) * g_ew[EMM + e2] * rsqrtf(g_deg_d[d]);
    } else {
        int e3 = e - EMM - EDD;
        g_src_g[g_ptr_g[ei[EG + e3]] + g_pos[e]] = ei[e3];
    }
}

// ---------------- register-tiled f32x2 GEMM ----------------
// MODE 0: GCN (row-split X/W select, W [K,Nout], no bias)
// MODE 1: dual (single X, Wa cols [0,nc0), Wb cols [nc0,nc0+nc1), out Y0/Y1)
// MODE 2: JK (X concat of x0/x1/x2 over k, single W, bias, out Y0)
// blockDim = (cols/8 <= 32, 8) => <= 256 threads. Wide Nout covered by gridDim.y.
// Per-thread 8 rows x 8 cols; grid.x = rows/64.
struct GArgs {
    const float* X0; const float* X1; const float* X2;
    int rowsplit, K;
    const float* Wa; const float* Wb; int nc0, nc1;
    const float* bias;
    float* Y0; float* Y1;
    int in_relu;
};
template <int MODE>
__global__ void __launch_bounds__(256) k_gemm(GArgs a) {
    extern __shared__ float Xs[];
    int tx = threadIdx.x, ty = threadIdx.y;
    int nth = blockDim.x * 8;
    int tid = ty * blockDim.x + tx;
    int rbase = blockIdx.x * MTILE;

    // per-block X / W selection
    const float* Xp = a.X0;
    const float* Wsel = a.Wa;
    int xrow0 = rbase;
    if (MODE == 0) {
        if (rbase >= a.rowsplit) { Xp = a.X1; Wsel = a.Wb; xrow0 = rbase - a.rowsplit; }
    }
    // per-thread W / out column routing (jg = global output column)
    int jg = (blockIdx.y * blockDim.x + tx) * 8;
    const float* Wth; int jloc, ldw;
    float* Yth; int ldo;
    if (MODE == 1) {
        if (jg < a.nc0) { Wth = a.Wa; jloc = jg; ldw = a.nc0; Yth = a.Y0; ldo = a.nc0; }
        else            { Wth = a.Wb; jloc = jg - a.nc0; ldw = a.nc1; Yth = a.Y1; ldo = a.nc1; }
    } else {
        Wth = Wsel; jloc = jg; ldw = a.nc0; Yth = a.Y0; ldo = a.nc0;
    }

    unsigned long long acc[4][8];
#pragma unroll
    for (int p = 0; p < 4; p++)
#pragma unroll
        for (int c = 0; c < 8; c++) acc[p][c] = 0ull;

    for (int k0 = 0; k0 < a.K; k0 += 128) {
        int kc = min(128, a.K - k0);
        if (k0) __syncthreads();
        for (int idx = tid; idx < kc * MTILE; idx += nth) {
            int k = idx % kc;
            int r = idx / kc;
            float v;
            if (MODE == 2) {
                int gk = k0 + k;
                int gr = rbase + r;
                if (gk < 128)      v = a.X0[(size_t)gr * 128 + gk];
                else if (gk < 192) v = a.X1[(size_t)gr * 64 + (gk - 128)];
                else               v = a.X2[(size_t)gr * 32 + (gk - 192)];
            } else {
                v = Xp[(size_t)(xrow0 + r) * a.K + k0 + k];
                if (MODE == 0 && a.in_relu) v = fmaxf(v, 0.f);
            }
            Xs[k * PAD + r] = v;
        }
        __syncthreads();
        for (int k = 0; k < kc; k++) {
            const ulonglong2* xv = (const ulonglong2*)&Xs[k * PAD + ty * 8];
            ulonglong2 ua = xv[0], ub = xv[1];
            unsigned long long xp[4] = {ua.x, ua.y, ub.x, ub.y};
            const float4* w4 = (const float4*)&Wth[(size_t)(k0 + k) * ldw + jloc];
            float4 wa = w4[0], wb = w4[1];
            unsigned long long wd[8];
            wd[0] = pk2(wa.x); wd[1] = pk2(wa.y); wd[2] = pk2(wa.z); wd[3] = pk2(wa.w);
            wd[4] = pk2(wb.x); wd[5] = pk2(wb.y); wd[6] = pk2(wb.z); wd[7] = pk2(wb.w);
#pragma unroll
            for (int c = 0; c < 8; c++)
#pragma unroll
                for (int p = 0; p < 4; p++) fma2(acc[p][c], xp[p], wd[c]);
        }
    }

    float bb[8];
#pragma unroll
    for (int c = 0; c < 8; c++) bb[c] = (MODE == 2) ? a.bias[jloc + c] : 0.f;
#pragma unroll
    for (int p = 0; p < 4; p++) {
        float o0[8], o1[8];
#pragma unroll
        for (int c = 0; c < 8; c++) {
            float2 f = upk(acc[p][c]);
            o0[c] = f.x + bb[c];
            o1[c] = f.y + bb[c];
        }
        int r0 = rbase + ty * 8 + 2 * p;
        float4* d0 = (float4*)&Yth[(size_t)r0 * ldo + jloc];
        float4* d1 = (float4*)&Yth[(size_t)(r0 + 1) * ldo + jloc];
        d0[0] = make_float4(o0[0], o0[1], o0[2], o0[3]);
        d0[1] = make_float4(o0[4], o0[5], o0[6], o0[7]);
        d1[0] = make_float4(o1[0], o1[1], o1[2], o1[3]);
        d1[1] = make_float4(o1[4], o1[5], o1[6], o1[7]);
    }
}

// ---------------- GCN aggregation (fused m+d, warp per node) ----------------
__global__ void k_gcn_agg(const float* __restrict__ bm, const float* __restrict__ bd,
                          const float* __restrict__ h, float* __restrict__ out,
                          int out_relu) {
    int w = (blockIdx.x * blockDim.x + threadIdx.x) >> 5;
    if (w >= NT) return;
    int lane = threadIdx.x & 31;
    bool isM = w < NM;
    int loc = isM ? w : w - NM;
    const int* ptr = isM ? g_ptr_mm : g_ptr_dd;
    const int* cs = isM ? g_src_mm : g_src_dd;
    const float* cn = isM ? g_nrm_mm : g_nrm_dd;
    const float* deg = isM ? g_deg_m : g_deg_d;
    const float* b = isM ? bm : bd;
    int hbase = isM ? 0 : NM;

    float di = rsqrtf(deg[loc]);
    float sc = di * di;
    float4 self = ((const float4*)h)[(size_t)w * 32 + lane];
    float4 bb = ((const float4*)b)[lane];
    float4 acc;
    acc.x = bb.x + self.x * sc;
    acc.y = bb.y + self.y * sc;
    acc.z = bb.z + self.z * sc;
    acc.w = bb.w + self.w * sc;
    int e1 = ptr[loc + 1];
    for (int e = ptr[loc]; e < e1; e++) {
        int s = cs[e];
        float nm = cn[e];
        float4 hv = ((const float4*)h)[(size_t)(hbase + s) * 32 + lane];
        acc.x += hv.x * nm;
        acc.y += hv.y * nm;
        acc.z += hv.z * nm;
        acc.w += hv.w * nm;
    }
    if (out_relu) {
        acc.x = fmaxf(acc.x, 0.f); acc.y = fmaxf(acc.y, 0.f);
        acc.z = fmaxf(acc.z, 0.f); acc.w = fmaxf(acc.w, 0.f);
    }
    ((float4*)out)[(size_t)w * 32 + lane] = acc;
}

// ---------------- fused GATv2 (warp per node, online softmax) ----------------
template <int C>
__global__ void k_gat_fused(const float* __restrict__ xl, const float* __restrict__ xr,
                            const float* __restrict__ att, const float* __restrict__ bias,
                            float* __restrict__ out, int elu) {
    constexpr int HC = 4 * C;
    constexpr int R = C / 8;
    int w = (blockIdx.x * blockDim.x + threadIdx.x) >> 5;
    if (w >= NT) return;
    int lane = threadIdx.x & 31;
    int hd = lane >> 3, c0 = lane & 7;
    int base = hd * C + c0;

    float attr[R], xrd[R], acc[R];
    const float* xrp = xr + (size_t)w * HC;
    const float* xlp = xl + (size_t)w * HC;
#pragma unroll
    for (int i = 0; i < R; i++) {
        attr[i] = att[base + 8 * i];
        xrd[i] = xrp[base + 8 * i];
    }
    float p = 0.f;
#pragma unroll
    for (int i = 0; i < R; i++) {
        float xv = xlp[base + 8 * i];
        acc[i] = xv;
        float v = xv + xrd[i];
        v = v > 0.f ? v : 0.2f * v;
        p += v * attr[i];
    }
    p += __shfl_xor_sync(0xffffffffu, p, 1);
    p += __shfl_xor_sync(0xffffffffu, p, 2);
    p += __shfl_xor_sync(0xffffffffu, p, 4);
    float m = p, ssum = 1.f;

    int e1 = g_ptr_g[w + 1];
    for (int e = g_ptr_g[w]; e < e1; e++) {
        int s = g_src_g[e];
        const float* xs = xl + (size_t)s * HC;
        float xv[R];
        float q = 0.f;
#pragma unroll
        for (int i = 0; i < R; i++) {
            xv[i] = xs[base + 8 * i];
            float v = xv[i] + xrd[i];
            v = v > 0.f ? v : 0.2f * v;
            q += v * attr[i];
        }
        q += __shfl_xor_sync(0xffffffffu, q, 1);
        q += __shfl_xor_sync(0xffffffffu, q, 2);
        q += __shfl_xor_sync(0xffffffffu, q, 4);
        float mn = fmaxf(m, q);
        float corr = __expf(m - mn);
        float wq = __expf(q - mn);
        ssum = ssum * corr + wq;
        m = mn;
#pragma unroll
        for (int i = 0; i < R; i++) acc[i] = acc[i] * corr + wq * xv[i];
    }
    float inv = 1.f / ssum;
#pragma unroll
    for (int i = 0; i < R; i++) {
        float t = acc[i] * inv;
        t += __shfl_xor_sync(0xffffffffu, t, 8);
        t += __shfl_xor_sync(0xffffffffu, t, 16);
        if (lane < 8) {
            float v = 0.25f * t + bias[c0 + 8 * i];
            if (elu) v = v > 0.f ? v : expm1f(v);
            out[(size_t)w * C + c0 + 8 * i] = v;
        }
    }
}

// ---------------- host orchestration ----------------
extern "C" void kernel_launch(void* const* d_in, const int* in_sizes, int n_in,
                              void* d_out, int out_size) {
    const float* mm_f = (const float*)d_in[0];
    const float* d_sf = (const float*)d_in[1];
    const float* ms   = (const float*)d_in[2];
    const float* ds   = (const float*)d_in[3];
    const int*   mme  = (const int*)d_in[4];
    const int*   dde  = (const int*)d_in[5];
    const int*   ei   = (const int*)d_in[6];
    const float* W_m1 = (const float*)d_in[7];
    const float* b_m1 = (const float*)d_in[8];
    const float* W_m2 = (const float*)d_in[9];
    const float* b_m2 = (const float*)d_in[10];
    const float* W_d1 = (const float*)d_in[11];
    const float* b_d1 = (const float*)d_in[12];
    const float* W_d2 = (const float*)d_in[13];
    const float* b_d2 = (const float*)d_in[14];
    const float* Wl1  = (const float*)d_in[15];
    const float* Wr1  = (const float*)d_in[16];
    const float* att1 = (const float*)d_in[17];
    const float* bia1 = (const float*)d_in[18];
    const float* Wl2  = (const float*)d_in[19];
    const float* Wr2  = (const float*)d_in[20];
    const float* att2 = (const float*)d_in[21];
    const float* bia2 = (const float*)d_in[22];
    const float* W_jk = (const float*)d_in[23];
    const float* b_jk = (const float*)d_in[24];

    void* vp;
    float *p_h, *p_xr, *p_tmp, *p_x0, *p_x1, *p_x2;
    cudaGetSymbolAddress(&vp, g_h);   p_h   = (float*)vp;
    cudaGetSymbolAddress(&vp, g_xr);  p_xr  = (float*)vp;
    cudaGetSymbolAddress(&vp, g_tmp); p_tmp = (float*)vp;
    cudaGetSymbolAddress(&vp, g_x0);  p_x0  = (float*)vp;
    cudaGetSymbolAddress(&vp, g_x1);  p_x1  = (float*)vp;
    cudaGetSymbolAddress(&vp, g_x2);  p_x2  = (float*)vp;

    const int SM128 = 128 * PAD * 4;   // shared bytes for kc=128
    const int SM64  = 64 * PAD * 4;

    // ---- CSR build (all three graphs) ----
    k_init<<<cdiv(NT, 256), 256>>>();
    k_build<<<cdiv(ETOT, 256), 256>>>(mme, dde, ei, ms, ds);
    k_scan3<<<3, 1024>>>();
    k_scatter<<<cdiv(ETOT, 256), 256>>>(mme, dde, ei);

    // ---- GCN layer 1 (m+d fused) ----
    GArgs a{};
    a.X0 = mm_f; a.X1 = d_sf; a.rowsplit = NM; a.K = 128;
    a.Wa = W_m1; a.Wb = W_d1; a.nc0 = 128; a.Y0 = p_h; a.in_relu = 0;
    k_gemm<0><<<dim3(NT / 64, 1), dim3(16, 8), SM128>>>(a);
    k_gcn_agg<<<cdiv(NT * 32, 256), 256>>>(b_m1, b_d1, p_h, p_tmp, 0);
    // ---- GCN layer 2 ----
    a.X0 = p_tmp; a.X1 = p_tmp + (size_t)NM * 128;
    a.Wa = W_m2; a.Wb = W_d2; a.in_relu = 1;
    k_gemm<0><<<dim3(NT / 64, 1), dim3(16, 8), SM128>>>(a);
    k_gcn_agg<<<cdiv(NT * 32, 256), 256>>>(b_m2, b_d2, p_h, p_x0, 1);

    // ---- GATv2 layer 1: x0 [NT,128] -> xl,xr [NT,256] (512 cols total, 2 col-tiles) ----
    GArgs g1{};
    g1.X0 = p_x0; g1.K = 128;
    g1.Wa = Wl1; g1.Wb = Wr1; g1.nc0 = 256; g1.nc1 = 256;
    g1.Y0 = p_h; g1.Y1 = p_xr;
    k_gemm<1><<<dim3(NT / 64, 2), dim3(32, 8), SM128>>>(g1);
    k_gat_fused<64><<<cdiv(NT * 32, 256), 256>>>(p_h, p_xr, att1, bia1, p_x1, 1);

    // ---- GATv2 layer 2: x1 [NT,64] -> xl,xr [NT,128] (256 cols total, 1 col-tile) ----
    GArgs g2{};
    g2.X0 = p_x1; g2.K = 64;
    g2.Wa = Wl2; g2.Wb = Wr2; g2.nc0 = 128; g2.nc1 = 128;
    g2.Y0 = p_h; g2.Y1 = p_xr;
    k_gemm<1><<<dim3(NT / 64, 1), dim3(32, 8), SM64>>>(g2);
    k_gat_fused<32><<<cdiv(NT * 32, 256), 256>>>(p_h, p_xr, att2, bia2, p_x2, 0);

    // ---- JK: concat(x0,x1,x2) @ W_jk + b_jk -> d_out ----
    GArgs aj{};
    aj.X0 = p_x0; aj.X1 = p_x1; aj.X2 = p_x2; aj.K = 224;
    aj.Wa = W_jk; aj.bias = b_jk; aj.nc0 = 128; aj.Y0 = (float*)d_out;
    k_gemm<2><<<dim3(NT / 64, 1), dim3(16, 8), SM128>>>(aj);
}

// round 10
// speedup vs baseline: 1.4521x; 1.4521x over previous
#include <cuda_runtime.h>
#include <math.h>

// ---------------- problem constants ----------------
static constexpr int NM  = 8192;
static constexpr int ND  = 6144;
static constexpr int NT  = 14336;      // NM + ND
static constexpr int EMM = 131072;
static constexpr int EDD = 98304;
static constexpr int EG  = 229376;
static constexpr int ETOT = EMM + EDD + EG;

// ---------------- device scratch ----------------
__device__ float g_ew[EMM + EDD];
__device__ float g_deg_m[NM];
__device__ float g_deg_d[ND];
__device__ float g_h[NT * 256];
__device__ float g_xr[NT * 256];
__device__ float g_tmp[NT * 128];
__device__ float g_x0[NT * 128];
__device__ float g_x1[NT * 64];
__device__ float g_x2[NT * 32];
__device__ int   g_cnt_m[NM];
__device__ int   g_cnt_d[ND];
__device__ int   g_cnt_g[NT];
__device__ int   g_pos[ETOT];
__device__ int   g_ptr_mm[NM + 1];
__device__ int   g_src_mm[EMM];
__device__ float g_nrm_mm[EMM];
__device__ int   g_ptr_dd[ND + 1];
__device__ int   g_src_dd[EDD];
__device__ float g_nrm_dd[EDD];
__device__ int   g_ptr_g[NT + 1];
__device__ int   g_src_g[EG];

static inline int cdiv(int a, int b) { return (a + b - 1) / b; }

// ---------------- setup kernels ----------------
__global__ void k_init() {
    int i = blockIdx.x * blockDim.x + threadIdx.x;
    if (i < NM) { g_cnt_m[i] = 0; g_deg_m[i] = 1.f; }
    if (i < ND) { g_cnt_d[i] = 0; g_deg_d[i] = 1.f; }
    if (i < NT) g_cnt_g[i] = 0;
}

__global__ void k_build(const int* __restrict__ mme, const int* __restrict__ dde,
                        const int* __restrict__ ei, const float* __restrict__ ms,
                        const float* __restrict__ ds) {
    int e = blockIdx.x * blockDim.x + threadIdx.x;
    if (e >= ETOT) return;
    if (e < EMM) {
        int s = mme[e], d = mme[EMM + e];
        float w = ms[(size_t)s * NM + d];
        g_ew[e] = w;
        atomicAdd(&g_deg_m[d], w);
        g_pos[e] = atomicAdd(&g_cnt_m[d], 1);
    } else if (e < EMM + EDD) {
        int e2 = e - EMM;
        int s = dde[e2], d = dde[EDD + e2];
        float w = ds[(size_t)s * ND + d];
        g_ew[EMM + e2] = w;
        atomicAdd(&g_deg_d[d], w);
        g_pos[e] = atomicAdd(&g_cnt_d[d], 1);
    } else {
        int e3 = e - EMM - EDD;
        int d = ei[EG + e3];
        g_pos[e] = atomicAdd(&g_cnt_g[d], 1);
    }
}

__device__ void scan_dev(const int* __restrict__ cnt, int* __restrict__ rowptr, int n) {
    __shared__ int sp[1024];
    int t = threadIdx.x;
    int per = (n + 1023) / 1024;
    int start = t * per;
    int vals[16];
    int local = 0;
    for (int j = 0; j < per; j++) {
        int i = start + j;
        vals[j] = (i < n) ? cnt[i] : 0;
        local += vals[j];
    }
    sp[t] = local;
    __syncthreads();
    for (int off = 1; off < 1024; off <<= 1) {
        int v = (t >= off) ? sp[t - off] : 0;
        __syncthreads();
        sp[t] += v;
        __syncthreads();
    }
    int ex = t ? sp[t - 1] : 0;
    for (int j = 0; j < per; j++) {
        int i = start + j;
        if (i < n) { rowptr[i] = ex; ex += vals[j]; }
    }
    if (t == 1023) rowptr[n] = sp[1023];
}
__global__ void k_scan3() {
    if (blockIdx.x == 0) scan_dev(g_cnt_m, g_ptr_mm, NM);
    else if (blockIdx.x == 1) scan_dev(g_cnt_d, g_ptr_dd, ND);
    else scan_dev(g_cnt_g, g_ptr_g, NT);
}

__global__ void k_scatter(const int* __restrict__ mme, const int* __restrict__ dde,
                          const int* __restrict__ ei) {
    int e = blockIdx.x * blockDim.x + threadIdx.x;
    if (e >= ETOT) return;
    if (e < EMM) {
        int s = mme[e], d = mme[EMM + e];
        int idx = g_ptr_mm[d] + g_pos[e];
        g_src_mm[idx] = s;
        g_nrm_mm[idx] = rsqrtf(g_deg_m[s]) * g_ew[e] * rsqrtf(g_deg_m[d]);
    } else if (e < EMM + EDD) {
        int e2 = e - EMM;
        int s = dde[e2], d = dde[EDD + e2];
        int idx = g_ptr_dd[d] + g_pos[e];
        g_src_dd[idx] = s;
        g_nrm_dd[idx] = rsqrtf(g_deg_d[s]) * g_ew[EMM + e2] * rsqrtf(g_deg_d[d]);
    } else {
        int e3 = e - EMM - EDD;
        g_src_g[g_ptr_g[ei[EG + e3]] + g_pos[e]] = ei[e3];
    }
}

// ---------------- transposed-smem scalar-FFMA GEMM ----------------
// MODE 0: GCN (row-split X/W select, W [K,nc0], no bias)
// MODE 1: dual (single X, Wa cols [0,nc0), Wb cols [nc0,nc0+nc1), out Y0/Y1)
// MODE 2: JK (X = concat(x0,x1,x2) over k, single W, bias, out Y0)
// 16 rows per block; each thread owns ONE output column and 16 rows.
// X tile transposed in smem: Xs[k*XST + r]; all threads broadcast-read the
// same 16 row values per k (4x LDS.128), W read coalesced (1 LDG per k).
struct GArgs {
    const float* X0; const float* X1; const float* X2;
    int rowsplit;
    const float* Wa; const float* Wb; int nc0, nc1;
    const float* bias;
    float* Y0; float* Y1;
    int in_relu;
};
template <int K, int MODE>
__global__ void __launch_bounds__(256) k_gemmT(GArgs a) {
    constexpr int RS = 16;       // rows per block
    constexpr int XST = 20;      // smem floats per k (16 + 4 pad, 16B-aligned)
    __shared__ float Xs[K * XST];
    int tx = threadIdx.x;
    int nth = blockDim.x;
    int rbase = blockIdx.x * RS;

    // per-block X / W selection (MODE 0 row split)
    const float* Xp = a.X0;
    const float* Wsel = a.Wa;
    int xrow0 = rbase;
    if (MODE == 0 && rbase >= a.rowsplit) {
        Xp = a.X1; Wsel = a.Wb; xrow0 = rbase - a.rowsplit;
    }
    // per-thread column routing
    int jg = blockIdx.y * nth + tx;
    const float* Wth; int jloc, ldw;
    float* Yth; int ldo;
    if (MODE == 1) {
        if (jg < a.nc0) { Wth = a.Wa; jloc = jg; ldw = a.nc0; Yth = a.Y0; ldo = a.nc0; }
        else            { Wth = a.Wb; jloc = jg - a.nc0; ldw = a.nc1; Yth = a.Y1; ldo = a.nc1; }
    } else {
        Wth = Wsel; jloc = jg; ldw = a.nc0; Yth = a.Y0; ldo = a.nc0;
    }

    // load X tile transposed (consecutive tx -> consecutive k: coalesced global reads)
    for (int idx = tx; idx < RS * K; idx += nth) {
        int k = idx % K;
        int r = idx / K;
        float v;
        if (MODE == 2) {
            int gr = rbase + r;
            if (k < 128)      v = a.X0[(size_t)gr * 128 + k];
            else if (k < 192) v = a.X1[(size_t)gr * 64 + (k - 128)];
            else              v = a.X2[(size_t)gr * 32 + (k - 192)];
        } else {
            v = Xp[(size_t)(xrow0 + r) * K + k];
            if (MODE == 0 && a.in_relu) v = fmaxf(v, 0.f);
        }
        Xs[k * XST + r] = v;
    }
    __syncthreads();

    float acc[RS];
#pragma unroll
    for (int r = 0; r < RS; r++) acc[r] = 0.f;

#pragma unroll 4
    for (int k = 0; k < K; k++) {
        const float4* xs4 = (const float4*)&Xs[k * XST];
        float4 x0 = xs4[0], x1 = xs4[1], x2 = xs4[2], x3 = xs4[3];
        float w = Wth[(size_t)k * ldw + jloc];
        acc[0]  += x0.x * w;  acc[1]  += x0.y * w;
        acc[2]  += x0.z * w;  acc[3]  += x0.w * w;
        acc[4]  += x1.x * w;  acc[5]  += x1.y * w;
        acc[6]  += x1.z * w;  acc[7]  += x1.w * w;
        acc[8]  += x2.x * w;  acc[9]  += x2.y * w;
        acc[10] += x2.z * w;  acc[11] += x2.w * w;
        acc[12] += x3.x * w;  acc[13] += x3.y * w;
        acc[14] += x3.z * w;  acc[15] += x3.w * w;
    }

    float bj = (MODE == 2) ? a.bias[jloc] : 0.f;
#pragma unroll
    for (int r = 0; r < RS; r++)
        Yth[(size_t)(rbase + r) * ldo + jloc] = acc[r] + bj;
}

// ---------------- GCN aggregation (fused m+d, warp per node) ----------------
__global__ void k_gcn_agg(const float* __restrict__ bm, const float* __restrict__ bd,
                          const float* __restrict__ h, float* __restrict__ out,
                          int out_relu) {
    int w = (blockIdx.x * blockDim.x + threadIdx.x) >> 5;
    if (w >= NT) return;
    int lane = threadIdx.x & 31;
    bool isM = w < NM;
    int loc = isM ? w : w - NM;
    const int* ptr = isM ? g_ptr_mm : g_ptr_dd;
    const int* cs = isM ? g_src_mm : g_src_dd;
    const float* cn = isM ? g_nrm_mm : g_nrm_dd;
    const float* deg = isM ? g_deg_m : g_deg_d;
    const float* b = isM ? bm : bd;
    int hbase = isM ? 0 : NM;

    float di = rsqrtf(deg[loc]);
    float sc = di * di;
    float4 self = ((const float4*)h)[(size_t)w * 32 + lane];
    float4 bb = ((const float4*)b)[lane];
    float4 acc;
    acc.x = bb.x + self.x * sc;
    acc.y = bb.y + self.y * sc;
    acc.z = bb.z + self.z * sc;
    acc.w = bb.w + self.w * sc;
    int e1 = ptr[loc + 1];
    for (int e = ptr[loc]; e < e1; e++) {
        int s = cs[e];
        float nm = cn[e];
        float4 hv = ((const float4*)h)[(size_t)(hbase + s) * 32 + lane];
        acc.x += hv.x * nm;
        acc.y += hv.y * nm;
        acc.z += hv.z * nm;
        acc.w += hv.w * nm;
    }
    if (out_relu) {
        acc.x = fmaxf(acc.x, 0.f); acc.y = fmaxf(acc.y, 0.f);
        acc.z = fmaxf(acc.z, 0.f); acc.w = fmaxf(acc.w, 0.f);
    }
    ((float4*)out)[(size_t)w * 32 + lane] = acc;
}

// ---------------- fused GATv2 (warp per node, online softmax) ----------------
template <int C>
__global__ void k_gat_fused(const float* __restrict__ xl, const float* __restrict__ xr,
                            const float* __restrict__ att, const float* __restrict__ bias,
                            float* __restrict__ out, int elu) {
    constexpr int HC = 4 * C;
    constexpr int R = C / 8;
    int w = (blockIdx.x * blockDim.x + threadIdx.x) >> 5;
    if (w >= NT) return;
    int lane = threadIdx.x & 31;
    int hd = lane >> 3, c0 = lane & 7;
    int base = hd * C + c0;

    float attr[R], xrd[R], acc[R];
    const float* xrp = xr + (size_t)w * HC;
    const float* xlp = xl + (size_t)w * HC;
#pragma unroll
    for (int i = 0; i < R; i++) {
        attr[i] = att[base + 8 * i];
        xrd[i] = xrp[base + 8 * i];
    }
    float p = 0.f;
#pragma unroll
    for (int i = 0; i < R; i++) {
        float xv = xlp[base + 8 * i];
        acc[i] = xv;
        float v = xv + xrd[i];
        v = v > 0.f ? v : 0.2f * v;
        p += v * attr[i];
    }
    p += __shfl_xor_sync(0xffffffffu, p, 1);
    p += __shfl_xor_sync(0xffffffffu, p, 2);
    p += __shfl_xor_sync(0xffffffffu, p, 4);
    float m = p, ssum = 1.f;

    int e1 = g_ptr_g[w + 1];
    for (int e = g_ptr_g[w]; e < e1; e++) {
        int s = g_src_g[e];
        const float* xs = xl + (size_t)s * HC;
        float xv[R];
        float q = 0.f;
#pragma unroll
        for (int i = 0; i < R; i++) {
            xv[i] = xs[base + 8 * i];
            float v = xv[i] + xrd[i];
            v = v > 0.f ? v : 0.2f * v;
            q += v * attr[i];
        }
        q += __shfl_xor_sync(0xffffffffu, q, 1);
        q += __shfl_xor_sync(0xffffffffu, q, 2);
        q += __shfl_xor_sync(0xffffffffu, q, 4);
        float mn = fmaxf(m, q);
        float corr = __expf(m - mn);
        float wq = __expf(q - mn);
        ssum = ssum * corr + wq;
        m = mn;
#pragma unroll
        for (int i = 0; i < R; i++) acc[i] = acc[i] * corr + wq * xv[i];
    }
    float inv = 1.f / ssum;
#pragma unroll
    for (int i = 0; i < R; i++) {
        float t = acc[i] * inv;
        t += __shfl_xor_sync(0xffffffffu, t, 8);
        t += __shfl_xor_sync(0xffffffffu, t, 16);
        if (lane < 8) {
            float v = 0.25f * t + bias[c0 + 8 * i];
            if (elu) v = v > 0.f ? v : expm1f(v);
            out[(size_t)w * C + c0 + 8 * i] = v;
        }
    }
}

// ---------------- host orchestration ----------------
extern "C" void kernel_launch(void* const* d_in, const int* in_sizes, int n_in,
                              void* d_out, int out_size) {
    const float* mm_f = (const float*)d_in[0];
    const float* d_sf = (const float*)d_in[1];
    const float* ms   = (const float*)d_in[2];
    const float* ds   = (const float*)d_in[3];
    const int*   mme  = (const int*)d_in[4];
    const int*   dde  = (const int*)d_in[5];
    const int*   ei   = (const int*)d_in[6];
    const float* W_m1 = (const float*)d_in[7];
    const float* b_m1 = (const float*)d_in[8];
    const float* W_m2 = (const float*)d_in[9];
    const float* b_m2 = (const float*)d_in[10];
    const float* W_d1 = (const float*)d_in[11];
    const float* b_d1 = (const float*)d_in[12];
    const float* W_d2 = (const float*)d_in[13];
    const float* b_d2 = (const float*)d_in[14];
    const float* Wl1  = (const float*)d_in[15];
    const float* Wr1  = (const float*)d_in[16];
    const float* att1 = (const float*)d_in[17];
    const float* bia1 = (const float*)d_in[18];
    const float* Wl2  = (const float*)d_in[19];
    const float* Wr2  = (const float*)d_in[20];
    const float* att2 = (const float*)d_in[21];
    const float* bia2 = (const float*)d_in[22];
    const float* W_jk = (const float*)d_in[23];
    const float* b_jk = (const float*)d_in[24];

    void* vp;
    float *p_h, *p_xr, *p_tmp, *p_x0, *p_x1, *p_x2;
    cudaGetSymbolAddress(&vp, g_h);   p_h   = (float*)vp;
    cudaGetSymbolAddress(&vp, g_xr);  p_xr  = (float*)vp;
    cudaGetSymbolAddress(&vp, g_tmp); p_tmp = (float*)vp;
    cudaGetSymbolAddress(&vp, g_x0);  p_x0  = (float*)vp;
    cudaGetSymbolAddress(&vp, g_x1);  p_x1  = (float*)vp;
    cudaGetSymbolAddress(&vp, g_x2);  p_x2  = (float*)vp;

    // ---- CSR build (all three graphs) ----
    k_init<<<cdiv(NT, 256), 256>>>();
    k_build<<<cdiv(ETOT, 256), 256>>>(mme, dde, ei, ms, ds);
    k_scan3<<<3, 1024>>>();
    k_scatter<<<cdiv(ETOT, 256), 256>>>(mme, dde, ei);

    const int GR = NT / 16;   // 896 row-blocks

    // ---- GCN layer 1 (m+d fused) ----
    GArgs a{};
    a.X0 = mm_f; a.X1 = d_sf; a.rowsplit = NM;
    a.Wa = W_m1; a.Wb = W_d1; a.nc0 = 128; a.Y0 = p_h; a.in_relu = 0;
    k_gemmT<128, 0><<<dim3(GR, 1), 128>>>(a);
    k_gcn_agg<<<cdiv(NT * 32, 256), 256>>>(b_m1, b_d1, p_h, p_tmp, 0);
    // ---- GCN layer 2 ----
    a.X0 = p_tmp; a.X1 = p_tmp + (size_t)NM * 128;
    a.Wa = W_m2; a.Wb = W_d2; a.in_relu = 1;
    k_gemmT<128, 0><<<dim3(GR, 1), 128>>>(a);
    k_gcn_agg<<<cdiv(NT * 32, 256), 256>>>(b_m2, b_d2, p_h, p_x0, 1);

    // ---- GATv2 layer 1: x0 [NT,128] -> xl,xr [NT,256] (512 cols, 2 col-tiles) ----
    GArgs g1{};
    g1.X0 = p_x0;
    g1.Wa = Wl1; g1.Wb = Wr1; g1.nc0 = 256; g1.nc1 = 256;
    g1.Y0 = p_h; g1.Y1 = p_xr;
    k_gemmT<128, 1><<<dim3(GR, 2), 256>>>(g1);
    k_gat_fused<64><<<cdiv(NT * 32, 256), 256>>>(p_h, p_xr, att1, bia1, p_x1, 1);

    // ---- GATv2 layer 2: x1 [NT,64] -> xl,xr [NT,128] (256 cols, 1 col-tile) ----
    GArgs g2{};
    g2.X0 = p_x1;
    g2.Wa = Wl2; g2.Wb = Wr2; g2.nc0 = 128; g2.nc1 = 128;
    g2.Y0 = p_h; g2.Y1 = p_xr;
    k_gemmT<64, 1><<<dim3(GR, 1), 256>>>(g2);
    k_gat_fused<32><<<cdiv(NT * 32, 256), 256>>>(p_h, p_xr, att2, bia2, p_x2, 0);

    // ---- JK: concat(x0,x1,x2) @ W_jk + b_jk -> d_out ----
    GArgs aj{};
    aj.X0 = p_x0; aj.X1 = p_x1; aj.X2 = p_x2;
    aj.Wa = W_jk; aj.bias = b_jk; aj.nc0 = 128; aj.Y0 = (float*)d_out;
    k_gemmT<224, 2><<<dim3(GR, 1), 128>>>(aj);
}

// round 12
// speedup vs baseline: 1.6428x; 1.1313x over previous
#include <cuda_runtime.h>
#include <math.h>

// ---------------- problem constants ----------------
static constexpr int NM  = 8192;
static constexpr int ND  = 6144;
static constexpr int NT  = 14336;      // NM + ND
static constexpr int EMM = 131072;
static constexpr int EDD = 98304;
static constexpr int EG  = 229376;
static constexpr int ETOT = EMM + EDD + EG;

// ---------------- device scratch ----------------
__device__ float g_ew[EMM + EDD];
__device__ float g_deg_m[NM];
__device__ float g_deg_d[ND];
__device__ float g_h[NT * 256];
__device__ float g_xr[NT * 256];
__device__ float g_tmp[NT * 128];
__device__ float g_x0[NT * 128];
__device__ float g_x1[NT * 64];
__device__ float g_x2[NT * 32];
__device__ int   g_cnt_m[NM];
__device__ int   g_cnt_d[ND];
__device__ int   g_cnt_g[NT];
__device__ int   g_pos[ETOT];
__device__ int   g_ptr_mm[NM + 1];
__device__ int   g_src_mm[EMM];
__device__ float g_nrm_mm[EMM];
__device__ int   g_ptr_dd[ND + 1];
__device__ int   g_src_dd[EDD];
__device__ float g_nrm_dd[EDD];
__device__ int   g_ptr_g[NT + 1];
__device__ int   g_src_g[EG];

static inline int cdiv(int a, int b) { return (a + b - 1) / b; }

// ---------------- f32x2 helpers ----------------
__device__ __forceinline__ unsigned long long pk2(float v) {
    unsigned long long r;
    asm("mov.b64 %0, {%1, %1};" : "=l"(r) : "f"(v));
    return r;
}
__device__ __forceinline__ void fma2(unsigned long long& d, unsigned long long a,
                                     unsigned long long b) {
    asm("fma.rn.f32x2 %0, %1, %2, %0;" : "+l"(d) : "l"(a), "l"(b));
}
__device__ __forceinline__ float2 upk(unsigned long long v) {
    float2 f;
    asm("mov.b64 {%0, %1}, %2;" : "=f"(f.x), "=f"(f.y) : "l"(v));
    return f;
}

// ---------------- setup kernels ----------------
__global__ void k_init() {
    int i = blockIdx.x * blockDim.x + threadIdx.x;
    if (i < NM) { g_cnt_m[i] = 0; g_deg_m[i] = 1.f; }
    if (i < ND) { g_cnt_d[i] = 0; g_deg_d[i] = 1.f; }
    if (i < NT) g_cnt_g[i] = 0;
}

__global__ void k_build(const int* __restrict__ mme, const int* __restrict__ dde,
                        const int* __restrict__ ei, const float* __restrict__ ms,
                        const float* __restrict__ ds) {
    int e = blockIdx.x * blockDim.x + threadIdx.x;
    if (e >= ETOT) return;
    if (e < EMM) {
        int s = mme[e], d = mme[EMM + e];
        float w = ms[(size_t)s * NM + d];
        g_ew[e] = w;
        atomicAdd(&g_deg_m[d], w);
        g_pos[e] = atomicAdd(&g_cnt_m[d], 1);
    } else if (e < EMM + EDD) {
        int e2 = e - EMM;
        int s = dde[e2], d = dde[EDD + e2];
        float w = ds[(size_t)s * ND + d];
        g_ew[EMM + e2] = w;
        atomicAdd(&g_deg_d[d], w);
        g_pos[e] = atomicAdd(&g_cnt_d[d], 1);
    } else {
        int e3 = e - EMM - EDD;
        int d = ei[EG + e3];
        g_pos[e] = atomicAdd(&g_cnt_g[d], 1);
    }
}

__device__ void scan_dev(const int* __restrict__ cnt, int* __restrict__ rowptr, int n) {
    __shared__ int sp[1024];
    int t = threadIdx.x;
    int per = (n + 1023) / 1024;
    int start = t * per;
    int vals[16];
    int local = 0;
    for (int j = 0; j < per; j++) {
        int i = start + j;
        vals[j] = (i < n) ? cnt[i] : 0;
        local += vals[j];
    }
    sp[t] = local;
    __syncthreads();
    for (int off = 1; off < 1024; off <<= 1) {
        int v = (t >= off) ? sp[t - off] : 0;
        __syncthreads();
        sp[t] += v;
        __syncthreads();
    }
    int ex = t ? sp[t - 1] : 0;
    for (int j = 0; j < per; j++) {
        int i = start + j;
        if (i < n) { rowptr[i] = ex; ex += vals[j]; }
    }
    if (t == 1023) rowptr[n] = sp[1023];
}
__global__ void k_scan3() {
    if (blockIdx.x == 0) scan_dev(g_cnt_m, g_ptr_mm, NM);
    else if (blockIdx.x == 1) scan_dev(g_cnt_d, g_ptr_dd, ND);
    else scan_dev(g_cnt_g, g_ptr_g, NT);
}

__global__ void k_scatter(const int* __restrict__ mme, const int* __restrict__ dde,
                          const int* __restrict__ ei) {
    int e = blockIdx.x * blockDim.x + threadIdx.x;
    if (e >= ETOT) return;
    if (e < EMM) {
        int s = mme[e], d = mme[EMM + e];
        int idx = g_ptr_mm[d] + g_pos[e];
        g_src_mm[idx] = s;
        g_nrm_mm[idx] = rsqrtf(g_deg_m[s]) * g_ew[e] * rsqrtf(g_deg_m[d]);
    } else if (e < EMM + EDD) {
        int e2 = e - EMM;
        int s = dde[e2], d = dde[EDD + e2];
        int idx = g_ptr_dd[d] + g_pos[e];
        g_src_dd[idx] = s;
        g_nrm_dd[idx] = rsqrtf(g_deg_d[s]) * g_ew[EMM + e2] * rsqrtf(g_deg_d[d]);
    } else {
        int e3 = e - EMM - EDD;
        g_src_g[g_ptr_g[ei[EG + e3]] + g_pos[e]] = ei[e3];
    }
}

// ---------------- transposed-smem f32x2 GEMM ----------------
// MODE 0: GCN (row-split X/W select, W [K,nc0], no bias)
// MODE 1: dual (single X, Wa cols [0,nc0), Wb cols [nc0,nc0+nc1), out Y0/Y1)
// MODE 2: JK (X = concat(x0,x1,x2) over k, single W, bias, out Y0)
// 16 rows per block; each thread owns TWO adjacent output columns.
// X tile transposed in smem (rows consecutive): one LDS.128 = 2 row-pairs
// as packed u64 — feeds fma.rn.f32x2 directly, no packing movs for X.
struct GArgs {
    const float* X0; const float* X1; const float* X2;
    int rowsplit;
    const float* Wa; const float* Wb; int nc0, nc1;
    const float* bias;
    float* Y0; float* Y1;
    int in_relu;
};
template <int K, int MODE>
__global__ void __launch_bounds__(256) k_gemmT(GArgs a) {
    constexpr int RS = 16;       // rows per block
    constexpr int XST = 20;      // smem floats per k (16 + 4 pad, 16B-aligned)
    __shared__ float Xs[K * XST];
    int tx = threadIdx.x;
    int nth = blockDim.x;
    int rbase = blockIdx.x * RS;

    // per-block X / W selection (MODE 0 row split)
    const float* Xp = a.X0;
    const float* Wsel = a.Wa;
    int xrow0 = rbase;
    if (MODE == 0 && rbase >= a.rowsplit) {
        Xp = a.X1; Wsel = a.Wb; xrow0 = rbase - a.rowsplit;
    }
    // per-thread column routing (2 adjacent columns per thread)
    int jg = (blockIdx.y * nth + tx) * 2;
    const float* Wth; int jloc, ldw;
    float* Yth; int ldo;
    if (MODE == 1) {
        if (jg < a.nc0) { Wth = a.Wa; jloc = jg; ldw = a.nc0; Yth = a.Y0; ldo = a.nc0; }
        else            { Wth = a.Wb; jloc = jg - a.nc0; ldw = a.nc1; Yth = a.Y1; ldo = a.nc1; }
    } else {
        Wth = Wsel; jloc = jg; ldw = a.nc0; Yth = a.Y0; ldo = a.nc0;
    }

    // load X tile transposed (consecutive tx -> consecutive k: coalesced reads)
    for (int idx = tx; idx < RS * K; idx += nth) {
        int k = idx % K;
        int r = idx / K;
        float v;
        if (MODE == 2) {
            int gr = rbase + r;
            if (k < 128)      v = a.X0[(size_t)gr * 128 + k];
            else if (k < 192) v = a.X1[(size_t)gr * 64 + (k - 128)];
            else              v = a.X2[(size_t)gr * 32 + (k - 192)];
        } else {
            v = Xp[(size_t)(xrow0 + r) * K + k];
            if (MODE == 0 && a.in_relu) v = fmaxf(v, 0.f);
        }
        Xs[k * XST + r] = v;
    }
    __syncthreads();

    // acc[p][c]: row-pair p (rows 2p,2p+1) x column c, packed f32x2
    unsigned long long acc[8][2];
#pragma unroll
    for (int p = 0; p < 8; p++) { acc[p][0] = 0ull; acc[p][1] = 0ull; }

#pragma unroll 4
    for (int k = 0; k < K; k++) {
        const ulonglong2* xv = (const ulonglong2*)&Xs[k * XST];
        ulonglong2 a0 = xv[0], a1 = xv[1], a2 = xv[2], a3 = xv[3];
        float2 wv = *(const float2*)&Wth[(size_t)k * ldw + jloc];
        unsigned long long w0 = pk2(wv.x), w1 = pk2(wv.y);
        fma2(acc[0][0], a0.x, w0);  fma2(acc[0][1], a0.x, w1);
        fma2(acc[1][0], a0.y, w0);  fma2(acc[1][1], a0.y, w1);
        fma2(acc[2][0], a1.x, w0);  fma2(acc[2][1], a1.x, w1);
        fma2(acc[3][0], a1.y, w0);  fma2(acc[3][1], a1.y, w1);
        fma2(acc[4][0], a2.x, w0);  fma2(acc[4][1], a2.x, w1);
        fma2(acc[5][0], a2.y, w0);  fma2(acc[5][1], a2.y, w1);
        fma2(acc[6][0], a3.x, w0);  fma2(acc[6][1], a3.x, w1);
        fma2(acc[7][0], a3.y, w0);  fma2(acc[7][1], a3.y, w1);
    }

    float b0 = 0.f, b1 = 0.f;
    if (MODE == 2) { b0 = a.bias[jloc]; b1 = a.bias[jloc + 1]; }
#pragma unroll
    for (int p = 0; p < 8; p++) {
        float2 c0 = upk(acc[p][0]);   // col jloc,   rows 2p / 2p+1
        float2 c1 = upk(acc[p][1]);   // col jloc+1, rows 2p / 2p+1
        float* y0 = &Yth[(size_t)(rbase + 2 * p) * ldo + jloc];
        float* y1 = &Yth[(size_t)(rbase + 2 * p + 1) * ldo + jloc];
        ((float2*)y0)[0] = make_float2(c0.x + b0, c1.x + b1);
        ((float2*)y1)[0] = make_float2(c0.y + b0, c1.y + b1);
    }
}

// ---------------- GCN aggregation (fused m+d, warp per node) ----------------
__global__ void k_gcn_agg(const float* __restrict__ bm, const float* __restrict__ bd,
                          const float* __restrict__ h, float* __restrict__ out,
                          int out_relu) {
    int w = (blockIdx.x * blockDim.x + threadIdx.x) >> 5;
    if (w >= NT) return;
    int lane = threadIdx.x & 31;
    bool isM = w < NM;
    int loc = isM ? w : w - NM;
    const int* ptr = isM ? g_ptr_mm : g_ptr_dd;
    const int* cs = isM ? g_src_mm : g_src_dd;
    const float* cn = isM ? g_nrm_mm : g_nrm_dd;
    const float* deg = isM ? g_deg_m : g_deg_d;
    const float* b = isM ? bm : bd;
    int hbase = isM ? 0 : NM;

    float di = rsqrtf(deg[loc]);
    float sc = di * di;
    float4 self = ((const float4*)h)[(size_t)w * 32 + lane];
    float4 bb = ((const float4*)b)[lane];
    float4 acc;
    acc.x = bb.x + self.x * sc;
    acc.y = bb.y + self.y * sc;
    acc.z = bb.z + self.z * sc;
    acc.w = bb.w + self.w * sc;
    int e1 = ptr[loc + 1];
    for (int e = ptr[loc]; e < e1; e++) {
        int s = cs[e];
        float nm = cn[e];
        float4 hv = ((const float4*)h)[(size_t)(hbase + s) * 32 + lane];
        acc.x += hv.x * nm;
        acc.y += hv.y * nm;
        acc.z += hv.z * nm;
        acc.w += hv.w * nm;
    }
    if (out_relu) {
        acc.x = fmaxf(acc.x, 0.f); acc.y = fmaxf(acc.y, 0.f);
        acc.z = fmaxf(acc.z, 0.f); acc.w = fmaxf(acc.w, 0.f);
    }
    ((float4*)out)[(size_t)w * 32 + lane] = acc;
}

// ---------------- fused GATv2 (warp per node, online softmax) ----------------
template <int C>
__global__ void k_gat_fused(const float* __restrict__ xl, const float* __restrict__ xr,
                            const float* __restrict__ att, const float* __restrict__ bias,
                            float* __restrict__ out, int elu) {
    constexpr int HC = 4 * C;
    constexpr int R = C / 8;
    int w = (blockIdx.x * blockDim.x + threadIdx.x) >> 5;
    if (w >= NT) return;
    int lane = threadIdx.x & 31;
    int hd = lane >> 3, c0 = lane & 7;
    int base = hd * C + c0;

    float attr[R], xrd[R], acc[R];
    const float* xrp = xr + (size_t)w * HC;
    const float* xlp = xl + (size_t)w * HC;
#pragma unroll
    for (int i = 0; i < R; i++) {
        attr[i] = att[base + 8 * i];
        xrd[i] = xrp[base + 8 * i];
    }
    float p = 0.f;
#pragma unroll
    for (int i = 0; i < R; i++) {
        float xv = xlp[base + 8 * i];
        acc[i] = xv;
        float v = xv + xrd[i];
        v = v > 0.f ? v : 0.2f * v;
        p += v * attr[i];
    }
    p += __shfl_xor_sync(0xffffffffu, p, 1);
    p += __shfl_xor_sync(0xffffffffu, p, 2);
    p += __shfl_xor_sync(0xffffffffu, p, 4);
    float m = p, ssum = 1.f;

    int e1 = g_ptr_g[w + 1];
    for (int e = g_ptr_g[w]; e < e1; e++) {
        int s = g_src_g[e];
        const float* xs = xl + (size_t)s * HC;
        float xv[R];
        float q = 0.f;
#pragma unroll
        for (int i = 0; i < R; i++) {
            xv[i] = xs[base + 8 * i];
            float v = xv[i] + xrd[i];
            v = v > 0.f ? v : 0.2f * v;
            q += v * attr[i];
        }
        q += __shfl_xor_sync(0xffffffffu, q, 1);
        q += __shfl_xor_sync(0xffffffffu, q, 2);
        q += __shfl_xor_sync(0xffffffffu, q, 4);
        float mn = fmaxf(m, q);
        float corr = __expf(m - mn);
        float wq = __expf(q - mn);
        ssum = ssum * corr + wq;
        m = mn;
#pragma unroll
        for (int i = 0; i < R; i++) acc[i] = acc[i] * corr + wq * xv[i];
    }
    float inv = 1.f / ssum;
#pragma unroll
    for (int i = 0; i < R; i++) {
        float t = acc[i] * inv;
        t += __shfl_xor_sync(0xffffffffu, t, 8);
        t += __shfl_xor_sync(0xffffffffu, t, 16);
        if (lane < 8) {
            float v = 0.25f * t + bias[c0 + 8 * i];
            if (elu) v = v > 0.f ? v : expm1f(v);
            out[(size_t)w * C + c0 + 8 * i] = v;
        }
    }
}

// ---------------- host orchestration ----------------
extern "C" void kernel_launch(void* const* d_in, const int* in_sizes, int n_in,
                              void* d_out, int out_size) {
    const float* mm_f = (const float*)d_in[0];
    const float* d_sf = (const float*)d_in[1];
    const float* ms   = (const float*)d_in[2];
    const float* ds   = (const float*)d_in[3];
    const int*   mme  = (const int*)d_in[4];
    const int*   dde  = (const int*)d_in[5];
    const int*   ei   = (const int*)d_in[6];
    const float* W_m1 = (const float*)d_in[7];
    const float* b_m1 = (const float*)d_in[8];
    const float* W_m2 = (const float*)d_in[9];
    const float* b_m2 = (const float*)d_in[10];
    const float* W_d1 = (const float*)d_in[11];
    const float* b_d1 = (const float*)d_in[12];
    const float* W_d2 = (const float*)d_in[13];
    const float* b_d2 = (const float*)d_in[14];
    const float* Wl1  = (const float*)d_in[15];
    const float* Wr1  = (const float*)d_in[16];
    const float* att1 = (const float*)d_in[17];
    const float* bia1 = (const float*)d_in[18];
    const float* Wl2  = (const float*)d_in[19];
    const float* Wr2  = (const float*)d_in[20];
    const float* att2 = (const float*)d_in[21];
    const float* bia2 = (const float*)d_in[22];
    const float* W_jk = (const float*)d_in[23];
    const float* b_jk = (const float*)d_in[24];

    void* vp;
    float *p_h, *p_xr, *p_tmp, *p_x0, *p_x1, *p_x2;
    cudaGetSymbolAddress(&vp, g_h);   p_h   = (float*)vp;
    cudaGetSymbolAddress(&vp, g_xr);  p_xr  = (float*)vp;
    cudaGetSymbolAddress(&vp, g_tmp); p_tmp = (float*)vp;
    cudaGetSymbolAddress(&vp, g_x0);  p_x0  = (float*)vp;
    cudaGetSymbolAddress(&vp, g_x1);  p_x1  = (float*)vp;
    cudaGetSymbolAddress(&vp, g_x2);  p_x2  = (float*)vp;

    // ---- CSR build (all three graphs) ----
    k_init<<<cdiv(NT, 256), 256>>>();
    k_build<<<cdiv(ETOT, 256), 256>>>(mme, dde, ei, ms, ds);
    k_scan3<<<3, 1024>>>();
    k_scatter<<<cdiv(ETOT, 256), 256>>>(mme, dde, ei);

    const int GR = NT / 16;   // 896 row-blocks

    // ---- GCN layer 1 (m+d fused): 128 cols -> 64 threads ----
    GArgs a{};
    a.X0 = mm_f; a.X1 = d_sf; a.rowsplit = NM;
    a.Wa = W_m1; a.Wb = W_d1; a.nc0 = 128; a.Y0 = p_h; a.in_relu = 0;
    k_gemmT<128, 0><<<dim3(GR, 1), 64>>>(a);
    k_gcn_agg<<<cdiv(NT * 32, 256), 256>>>(b_m1, b_d1, p_h, p_tmp, 0);
    // ---- GCN layer 2 ----
    a.X0 = p_tmp; a.X1 = p_tmp + (size_t)NM * 128;
    a.Wa = W_m2; a.Wb = W_d2; a.in_relu = 1;
    k_gemmT<128, 0><<<dim3(GR, 1), 64>>>(a);
    k_gcn_agg<<<cdiv(NT * 32, 256), 256>>>(b_m2, b_d2, p_h, p_x0, 1);

    // ---- GATv2 layer 1: x0 [NT,128] -> xl,xr [NT,256] (512 cols -> 256 threads) ----
    GArgs g1{};
    g1.X0 = p_x0;
    g1.Wa = Wl1; g1.Wb = Wr1; g1.nc0 = 256; g1.nc1 = 256;
    g1.Y0 = p_h; g1.Y1 = p_xr;
    k_gemmT<128, 1><<<dim3(GR, 1), 256>>>(g1);
    k_gat_fused<64><<<cdiv(NT * 32, 256), 256>>>(p_h, p_xr, att1, bia1, p_x1, 1);

    // ---- GATv2 layer 2: x1 [NT,64] -> xl,xr [NT,128] (256 cols -> 128 threads) ----
    GArgs g2{};
    g2.X0 = p_x1;
    g2.Wa = Wl2; g2.Wb = Wr2; g2.nc0 = 128; g2.nc1 = 128;
    g2.Y0 = p_h; g2.Y1 = p_xr;
    k_gemmT<64, 1><<<dim3(GR, 1), 128>>>(g2);
    k_gat_fused<32><<<cdiv(NT * 32, 256), 256>>>(p_h, p_xr, att2, bia2, p_x2, 0);

    // ---- JK: concat(x0,x1,x2) @ W_jk + b_jk -> d_out (128 cols -> 64 threads) ----
    GArgs aj{};
    aj.X0 = p_x0; aj.X1 = p_x1; aj.X2 = p_x2;
    aj.Wa = W_jk; aj.bias = b_jk; aj.nc0 = 128; aj.Y0 = (float*)d_out;
    k_gemmT<224, 2><<<dim3(GR, 1), 64>>>(aj);
}

// round 16
// speedup vs baseline: 1.7584x; 1.0704x over previous
#include <cuda_runtime.h>
#include <math.h>

// ---------------- problem constants ----------------
static constexpr int NM  = 8192;
static constexpr int ND  = 6144;
static constexpr int NT  = 14336;      // NM + ND
static constexpr int EMM = 131072;
static constexpr int EDD = 98304;
static constexpr int EG  = 229376;
static constexpr int ETOT = EMM + EDD + EG;

// ---------------- device scratch ----------------
__device__ float g_ew[EMM + EDD];
__device__ float g_deg_m[NM];
__device__ float g_deg_d[ND];
__device__ float g_h[NT * 256];
__device__ float g_xr[NT * 256];
__device__ float g_tmp[NT * 128];
__device__ float g_x0[NT * 128];
__device__ float g_x1[NT * 64];
__device__ float g_x2[NT * 32];
__device__ int   g_cnt_m[NM];
__device__ int   g_cnt_d[ND];
__device__ int   g_cnt_g[NT];
__device__ int   g_pos[ETOT];
__device__ int   g_ptr_mm[NM + 1];
__device__ int   g_src_mm[EMM];
__device__ float g_nrm_mm[EMM];
__device__ int   g_ptr_dd[ND + 1];
__device__ int   g_src_dd[EDD];
__device__ float g_nrm_dd[EDD];
__device__ int   g_ptr_g[NT + 1];
__device__ int   g_src_g[EG];

static inline int cdiv(int a, int b) { return (a + b - 1) / b; }

// ---------------- f32x2 helpers ----------------
__device__ __forceinline__ unsigned long long pk2(float v) {
    unsigned long long r;
    asm("mov.b64 %0, {%1, %1};" : "=l"(r) : "f"(v));
    return r;
}
__device__ __forceinline__ void fma2(unsigned long long& d, unsigned long long a,
                                     unsigned long long b) {
    asm("fma.rn.f32x2 %0, %1, %2, %0;" : "+l"(d) : "l"(a), "l"(b));
}
__device__ __forceinline__ float2 upk(unsigned long long v) {
    float2 f;
    asm("mov.b64 {%0, %1}, %2;" : "=f"(f.x), "=f"(f.y) : "l"(v));
    return f;
}

// ---------------- setup kernels ----------------
__global__ void k_init() {
    int i = blockIdx.x * blockDim.x + threadIdx.x;
    if (i < NM) { g_cnt_m[i] = 0; g_deg_m[i] = 1.f; }
    if (i < ND) { g_cnt_d[i] = 0; g_deg_d[i] = 1.f; }
    if (i < NT) g_cnt_g[i] = 0;
}

__global__ void k_build(const int* __restrict__ mme, const int* __restrict__ dde,
                        const int* __restrict__ ei, const float* __restrict__ ms,
                        const float* __restrict__ ds) {
    int e = blockIdx.x * blockDim.x + threadIdx.x;
    if (e >= ETOT) return;
    if (e < EMM) {
        int s = mme[e], d = mme[EMM + e];
        float w = ms[(size_t)s * NM + d];
        g_ew[e] = w;
        atomicAdd(&g_deg_m[d], w);
        g_pos[e] = atomicAdd(&g_cnt_m[d], 1);
    } else if (e < EMM + EDD) {
        int e2 = e - EMM;
        int s = dde[e2], d = dde[EDD + e2];
        float w = ds[(size_t)s * ND + d];
        g_ew[EMM + e2] = w;
        atomicAdd(&g_deg_d[d], w);
        g_pos[e] = atomicAdd(&g_cnt_d[d], 1);
    } else {
        int e3 = e - EMM - EDD;
        int d = ei[EG + e3];
        g_pos[e] = atomicAdd(&g_cnt_g[d], 1);
    }
}

__device__ void scan_dev(const int* __restrict__ cnt, int* __restrict__ rowptr, int n) {
    __shared__ int sp[1024];
    int t = threadIdx.x;
    int per = (n + 1023) / 1024;
    int start = t * per;
    int vals[16];
    int local = 0;
    for (int j = 0; j < per; j++) {
        int i = start + j;
        vals[j] = (i < n) ? cnt[i] : 0;
        local += vals[j];
    }
    sp[t] = local;
    __syncthreads();
    for (int off = 1; off < 1024; off <<= 1) {
        int v = (t >= off) ? sp[t - off] : 0;
        __syncthreads();
        sp[t] += v;
        __syncthreads();
    }
    int ex = t ? sp[t - 1] : 0;
    for (int j = 0; j < per; j++) {
        int i = start + j;
        if (i < n) { rowptr[i] = ex; ex += vals[j]; }
    }
    if (t == 1023) rowptr[n] = sp[1023];
}
__global__ void k_scan3() {
    if (blockIdx.x == 0) scan_dev(g_cnt_m, g_ptr_mm, NM);
    else if (blockIdx.x == 1) scan_dev(g_cnt_d, g_ptr_dd, ND);
    else scan_dev(g_cnt_g, g_ptr_g, NT);
}

__global__ void k_scatter(const int* __restrict__ mme, const int* __restrict__ dde,
                          const int* __restrict__ ei) {
    int e = blockIdx.x * blockDim.x + threadIdx.x;
    if (e >= ETOT) return;
    if (e < EMM) {
        int s = mme[e], d = mme[EMM + e];
        int idx = g_ptr_mm[d] + g_pos[e];
        g_src_mm[idx] = s;
        g_nrm_mm[idx] = rsqrtf(g_deg_m[s]) * g_ew[e] * rsqrtf(g_deg_m[d]);
    } else if (e < EMM + EDD) {
        int e2 = e - EMM;
        int s = dde[e2], d = dde[EDD + e2];
        int idx = g_ptr_dd[d] + g_pos[e];
        g_src_dd[idx] = s;
        g_nrm_dd[idx] = rsqrtf(g_deg_d[s]) * g_ew[EMM + e2] * rsqrtf(g_deg_d[d]);
    } else {
        int e3 = e - EMM - EDD;
        g_src_g[g_ptr_g[ei[EG + e3]] + g_pos[e]] = ei[e3];
    }
}

// ---------------- transposed-smem f32x2 GEMM ----------------
// MODE 0: GCN (row-split X/W select, W [K,nc0], no bias)
// MODE 1: dual (single X, Wa cols [0,nc0), Wb cols [nc0,nc0+nc1), out Y0/Y1)
// MODE 2: JK (X = concat(x0,x1,x2) over k, single W, bias, out Y0)
// RS rows per block; each thread owns TWO adjacent output columns.
// X tile transposed in smem (rows consecutive): one LDS.128 = 2 row-pairs
// as packed u64 — feeds fma.rn.f32x2 directly, no packing movs for X.
struct GArgs {
    const float* X0; const float* X1; const float* X2;
    int rowsplit;
    const float* Wa; const float* Wb; int nc0, nc1;
    const float* bias;
    float* Y0; float* Y1;
    int in_relu;
};
template <int K, int MODE, int RS>
__global__ void __launch_bounds__(256) k_gemmT(GArgs a) {
    constexpr int XST = RS + 4;  // smem floats per k (pad keeps 16B align)
    __shared__ float Xs[K * XST];
    int tx = threadIdx.x;
    int nth = blockDim.x;
    int rbase = blockIdx.x * RS;

    // per-block X / W selection (MODE 0 row split)
    const float* Xp = a.X0;
    const float* Wsel = a.Wa;
    int xrow0 = rbase;
    if (MODE == 0 && rbase >= a.rowsplit) {
        Xp = a.X1; Wsel = a.Wb; xrow0 = rbase - a.rowsplit;
    }
    // per-thread column routing (2 adjacent columns per thread)
    int jg = (blockIdx.y * nth + tx) * 2;
    const float* Wth; int jloc, ldw;
    float* Yth; int ldo;
    if (MODE == 1) {
        if (jg < a.nc0) { Wth = a.Wa; jloc = jg; ldw = a.nc0; Yth = a.Y0; ldo = a.nc0; }
        else            { Wth = a.Wb; jloc = jg - a.nc0; ldw = a.nc1; Yth = a.Y1; ldo = a.nc1; }
    } else {
        Wth = Wsel; jloc = jg; ldw = a.nc0; Yth = a.Y0; ldo = a.nc0;
    }

    // load X tile transposed (consecutive tx -> consecutive k: coalesced reads)
    for (int idx = tx; idx < RS * K; idx += nth) {
        int k = idx % K;
        int r = idx / K;
        float v;
        if (MODE == 2) {
            int gr = rbase + r;
            if (k < 128)      v = a.X0[(size_t)gr * 128 + k];
            else if (k < 192) v = a.X1[(size_t)gr * 64 + (k - 128)];
            else              v = a.X2[(size_t)gr * 32 + (k - 192)];
        } else {
            v = Xp[(size_t)(xrow0 + r) * K + k];
            if (MODE == 0 && a.in_relu) v = fmaxf(v, 0.f);
        }
        Xs[k * XST + r] = v;
    }
    __syncthreads();

    // acc[p][c]: row-pair p (rows 2p,2p+1) x column c, packed f32x2
    unsigned long long acc[RS / 2][2];
#pragma unroll
    for (int p = 0; p < RS / 2; p++) { acc[p][0] = 0ull; acc[p][1] = 0ull; }

#pragma unroll 4
    for (int k = 0; k < K; k++) {
        const ulonglong2* xv = (const ulonglong2*)&Xs[k * XST];
        float2 wv = *(const float2*)&Wth[(size_t)k * ldw + jloc];
        unsigned long long w0 = pk2(wv.x), w1 = pk2(wv.y);
#pragma unroll
        for (int q = 0; q < RS / 4; q++) {
            ulonglong2 u = xv[q];
            fma2(acc[2 * q][0], u.x, w0);      fma2(acc[2 * q][1], u.x, w1);
            fma2(acc[2 * q + 1][0], u.y, w0);  fma2(acc[2 * q + 1][1], u.y, w1);
        }
    }

    float b0 = 0.f, b1 = 0.f;
    if (MODE == 2) { b0 = a.bias[jloc]; b1 = a.bias[jloc + 1]; }
#pragma unroll
    for (int p = 0; p < RS / 2; p++) {
        float2 c0 = upk(acc[p][0]);   // col jloc,   rows 2p / 2p+1
        float2 c1 = upk(acc[p][1]);   // col jloc+1, rows 2p / 2p+1
        float* y0 = &Yth[(size_t)(rbase + 2 * p) * ldo + jloc];
        float* y1 = &Yth[(size_t)(rbase + 2 * p + 1) * ldo + jloc];
        ((float2*)y0)[0] = make_float2(c0.x + b0, c1.x + b1);
        ((float2*)y1)[0] = make_float2(c0.y + b0, c1.y + b1);
    }
}

// ---------------- GCN aggregation (fused m+d, warp per node) ----------------
__global__ void k_gcn_agg(const float* __restrict__ bm, const float* __restrict__ bd,
                          const float* __restrict__ h, float* __restrict__ out,
                          int out_relu) {
    int w = (blockIdx.x * blockDim.x + threadIdx.x) >> 5;
    if (w >= NT) return;
    int lane = threadIdx.x & 31;
    bool isM = w < NM;
    int loc = isM ? w : w - NM;
    const int* ptr = isM ? g_ptr_mm : g_ptr_dd;
    const int* cs = isM ? g_src_mm : g_src_dd;
    const float* cn = isM ? g_nrm_mm : g_nrm_dd;
    const float* deg = isM ? g_deg_m : g_deg_d;
    const float* b = isM ? bm : bd;
    int hbase = isM ? 0 : NM;

    float di = rsqrtf(deg[loc]);
    float sc = di * di;
    float4 self = ((const float4*)h)[(size_t)w * 32 + lane];
    float4 bb = ((const float4*)b)[lane];
    float4 acc;
    acc.x = bb.x + self.x * sc;
    acc.y = bb.y + self.y * sc;
    acc.z = bb.z + self.z * sc;
    acc.w = bb.w + self.w * sc;
    int e1 = ptr[loc + 1];
    for (int e = ptr[loc]; e < e1; e++) {
        int s = cs[e];
        float nm = cn[e];
        float4 hv = ((const float4*)h)[(size_t)(hbase + s) * 32 + lane];
        acc.x += hv.x * nm;
        acc.y += hv.y * nm;
        acc.z += hv.z * nm;
        acc.w += hv.w * nm;
    }
    if (out_relu) {
        acc.x = fmaxf(acc.x, 0.f); acc.y = fmaxf(acc.y, 0.f);
        acc.z = fmaxf(acc.z, 0.f); acc.w = fmaxf(acc.w, 0.f);
    }
    ((float4*)out)[(size_t)w * 32 + lane] = acc;
}

// ---------------- fused GATv2 (warp per node, online softmax) ----------------
template <int C>
__global__ void k_gat_fused(const float* __restrict__ xl, const float* __restrict__ xr,
                            const float* __restrict__ att, const float* __restrict__ bias,
                            float* __restrict__ out, int elu) {
    constexpr int HC = 4 * C;
    constexpr int R = C / 8;
    int w = (blockIdx.x * blockDim.x + threadIdx.x) >> 5;
    if (w >= NT) return;
    int lane = threadIdx.x & 31;
    int hd = lane >> 3, c0 = lane & 7;
    int base = hd * C + c0;

    float attr[R], xrd[R], acc[R];
    const float* xrp = xr + (size_t)w * HC;
    const float* xlp = xl + (size_t)w * HC;
#pragma unroll
    for (int i = 0; i < R; i++) {
        attr[i] = att[base + 8 * i];
        xrd[i] = xrp[base + 8 * i];
    }
    float p = 0.f;
#pragma unroll
    for (int i = 0; i < R; i++) {
        float xv = xlp[base + 8 * i];
        acc[i] = xv;
        float v = xv + xrd[i];
        v = v > 0.f ? v : 0.2f * v;
        p += v * attr[i];
    }
    p += __shfl_xor_sync(0xffffffffu, p, 1);
    p += __shfl_xor_sync(0xffffffffu, p, 2);
    p += __shfl_xor_sync(0xffffffffu, p, 4);
    float m = p, ssum = 1.f;

    int e1 = g_ptr_g[w + 1];
    for (int e = g_ptr_g[w]; e < e1; e++) {
        int s = g_src_g[e];
        const float* xs = xl + (size_t)s * HC;
        float xv[R];
        float q = 0.f;
#pragma unroll
        for (int i = 0; i < R; i++) {
            xv[i] = xs[base + 8 * i];
            float v = xv[i] + xrd[i];
            v = v > 0.f ? v : 0.2f * v;
            q += v * attr[i];
        }
        q += __shfl_xor_sync(0xffffffffu, q, 1);
        q += __shfl_xor_sync(0xffffffffu, q, 2);
        q += __shfl_xor_sync(0xffffffffu, q, 4);
        float mn = fmaxf(m, q);
        float corr = __expf(m - mn);
        float wq = __expf(q - mn);
        ssum = ssum * corr + wq;
        m = mn;
#pragma unroll
        for (int i = 0; i < R; i++) acc[i] = acc[i] * corr + wq * xv[i];
    }
    float inv = 1.f / ssum;
#pragma unroll
    for (int i = 0; i < R; i++) {
        float t = acc[i] * inv;
        t += __shfl_xor_sync(0xffffffffu, t, 8);
        t += __shfl_xor_sync(0xffffffffu, t, 16);
        if (lane < 8) {
            float v = 0.25f * t + bias[c0 + 8 * i];
            if (elu) v = v > 0.f ? v : expm1f(v);
            out[(size_t)w * C + c0 + 8 * i] = v;
        }
    }
}

// ---------------- host orchestration ----------------
extern "C" void kernel_launch(void* const* d_in, const int* in_sizes, int n_in,
                              void* d_out, int out_size) {
    const float* mm_f = (const float*)d_in[0];
    const float* d_sf = (const float*)d_in[1];
    const float* ms   = (const float*)d_in[2];
    const float* ds   = (const float*)d_in[3];
    const int*   mme  = (const int*)d_in[4];
    const int*   dde  = (const int*)d_in[5];
    const int*   ei   = (const int*)d_in[6];
    const float* W_m1 = (const float*)d_in[7];
    const float* b_m1 = (const float*)d_in[8];
    const float* W_m2 = (const float*)d_in[9];
    const float* b_m2 = (const float*)d_in[10];
    const float* W_d1 = (const float*)d_in[11];
    const float* b_d1 = (const float*)d_in[12];
    const float* W_d2 = (const float*)d_in[13];
    const float* b_d2 = (const float*)d_in[14];
    const float* Wl1  = (const float*)d_in[15];
    const float* Wr1  = (const float*)d_in[16];
    const float* att1 = (const float*)d_in[17];
    const float* bia1 = (const float*)d_in[18];
    const float* Wl2  = (const float*)d_in[19];
    const float* Wr2  = (const float*)d_in[20];
    const float* att2 = (const float*)d_in[21];
    const float* bia2 = (const float*)d_in[22];
    const float* W_jk = (const float*)d_in[23];
    const float* b_jk = (const float*)d_in[24];

    void* vp;
    float *p_h, *p_xr, *p_tmp, *p_x0, *p_x1, *p_x2;
    cudaGetSymbolAddress(&vp, g_h);   p_h   = (float*)vp;
    cudaGetSymbolAddress(&vp, g_xr);  p_xr  = (float*)vp;
    cudaGetSymbolAddress(&vp, g_tmp); p_tmp = (float*)vp;
    cudaGetSymbolAddress(&vp, g_x0);  p_x0  = (float*)vp;
    cudaGetSymbolAddress(&vp, g_x1);  p_x1  = (float*)vp;
    cudaGetSymbolAddress(&vp, g_x2);  p_x2  = (float*)vp;

    // ---- CSR build (all three graphs) ----
    k_init<<<cdiv(NT, 256), 256>>>();
    k_build<<<cdiv(ETOT, 256), 256>>>(mme, dde, ei, ms, ds);
    k_scan3<<<3, 1024>>>();
    k_scatter<<<cdiv(ETOT, 256), 256>>>(mme, dde, ei);

    // ---- GCN layer 1 (m+d fused): 128 cols -> 64 threads, RS=16 ----
    GArgs a{};
    a.X0 = mm_f; a.X1 = d_sf; a.rowsplit = NM;
    a.Wa = W_m1; a.Wb = W_d1; a.nc0 = 128; a.Y0 = p_h; a.in_relu = 0;
    k_gemmT<128, 0, 16><<<dim3(NT / 16, 1), 64>>>(a);
    k_gcn_agg<<<cdiv(NT * 32, 256), 256>>>(b_m1, b_d1, p_h, p_tmp, 0);
    // ---- GCN layer 2 ----
    a.X0 = p_tmp; a.X1 = p_tmp + (size_t)NM * 128;
    a.Wa = W_m2; a.Wb = W_d2; a.in_relu = 1;
    k_gemmT<128, 0, 16><<<dim3(NT / 16, 1), 64>>>(a);
    k_gcn_agg<<<cdiv(NT * 32, 256), 256>>>(b_m2, b_d2, p_h, p_x0, 1);

    // ---- GATv2 layer 1: x0 [NT,128] -> xl,xr [NT,256] (512 cols -> 256 thr, RS=32) ----
    GArgs g1{};
    g1.X0 = p_x0;
    g1.Wa = Wl1; g1.Wb = Wr1; g1.nc0 = 256; g1.nc1 = 256;
    g1.Y0 = p_h; g1.Y1 = p_xr;
    k_gemmT<128, 1, 32><<<dim3(NT / 32, 1), 256>>>(g1);
    k_gat_fused<64><<<cdiv(NT * 32, 256), 256>>>(p_h, p_xr, att1, bia1, p_x1, 1);

    // ---- GATv2 layer 2: x1 [NT,64] -> xl,xr [NT,128] (256 cols -> 128 thr, RS=32) ----
    GArgs g2{};
    g2.X0 = p_x1;
    g2.Wa = Wl2; g2.Wb = Wr2; g2.nc0 = 128; g2.nc1 = 128;
    g2.Y0 = p_h; g2.Y1 = p_xr;
    k_gemmT<64, 1, 32><<<dim3(NT / 32, 1), 128>>>(g2);
    k_gat_fused<32><<<cdiv(NT * 32, 256), 256>>>(p_h, p_xr, att2, bia2, p_x2, 0);

    // ---- JK: concat(x0,x1,x2) @ W_jk + b_jk -> d_out (128 cols -> 64 thr, RS=16) ----
    GArgs aj{};
    aj.X0 = p_x0; aj.X1 = p_x1; aj.X2 = p_x2;
    aj.Wa = W_jk; aj.bias = b_jk; aj.nc0 = 128; aj.Y0 = (float*)d_out;
    k_gemmT<224, 2, 16><<<dim3(NT / 16, 1), 64>>>(aj);
}